// round 3
// baseline (speedup 1.0000x reference)
#include <cuda_runtime.h>
#include <math.h>

#define NMAX 8192
#define KMAX 64
#define ICHUNKS 16
#define TILE (NMAX / ICHUNKS)   // 512
#define BLK 256

// Scratch (allocation-free rule: __device__ globals)
__device__ float g_coefA[KMAX];          // w_k / sqrt(2*pi*var_k)
__device__ float g_coefB[KMAX];          // -0.5 / var_k
__device__ float g_part[ICHUNKS * NMAX]; // per-(i-chunk, j) partial KDE sums

__device__ __forceinline__ float ex2f(float e) {
    float r;
    asm("ex2.approx.ftz.f32 %0, %1;" : "=f"(r) : "f"(e));
    return r;
}

// ---------------------------------------------------------------------------
// Kernel 0: softmax(weight_logits), component coefficients, zero the output.
// ---------------------------------------------------------------------------
__global__ void k_prep(const float* __restrict__ wl,
                       const float* __restrict__ lv,
                       float* __restrict__ out, int K) {
    __shared__ float sh[KMAX];
    int t = threadIdx.x;

    float w = (t < K) ? wl[t] : -INFINITY;
    sh[t] = w;
    __syncthreads();
#pragma unroll
    for (int o = KMAX / 2; o > 0; o >>= 1) {
        if (t < o) sh[t] = fmaxf(sh[t], sh[t + o]);
        __syncthreads();
    }
    float m = sh[0];
    __syncthreads();

    float e = (t < K) ? __expf(w - m) : 0.0f;
    sh[t] = e;
    __syncthreads();
#pragma unroll
    for (int o = KMAX / 2; o > 0; o >>= 1) {
        if (t < o) sh[t] += sh[t + o];
        __syncthreads();
    }
    float wt = e / sh[0];

    if (t < K) {
        float var = __expf(lv[t]);
        g_coefA[t] = wt * rsqrtf(2.0f * (float)M_PI * var);
        g_coefB[t] = -0.5f / var;
    }
    if (t == 0) *out = 0.0f;
}

// ---------------------------------------------------------------------------
// Kernel 1: dense pairwise KDE partial sums, in exp2 domain.
// x is pre-scaled by s = sqrt(-Ckde*log2(e)) at tile-load time, so the inner
// body is: d = xj' - xi';  acc += ex2(-d*d).   (4 instrs, MUFU-bound)
// grid = (n/BLK, ICHUNKS).
// ---------------------------------------------------------------------------
__global__ void k_kde(const float* __restrict__ x, int n, float scaleS) {
    __shared__ float xs[TILE];
    int j  = blockIdx.x * BLK + threadIdx.x;
    int i0 = blockIdx.y * TILE;

    for (int t = threadIdx.x; t < TILE; t += BLK) {
        int i = i0 + t;
        xs[t] = (i < n) ? x[i] * scaleS : 3.0e18f;  // pad -> -d*d = -inf -> 0
    }
    __syncthreads();

    float xj = ((j < n) ? x[j] : 0.0f) * scaleS;

    // four accumulators: MUFU lat=16, rt=8 -> keep the FADD chains off the
    // critical path
    float s0 = 0.0f, s1 = 0.0f, s2 = 0.0f, s3 = 0.0f;
#pragma unroll 8
    for (int ii = 0; ii < TILE; ii += 4) {
        float d0 = xj - xs[ii];
        float d1 = xj - xs[ii + 1];
        float d2 = xj - xs[ii + 2];
        float d3 = xj - xs[ii + 3];
        s0 += ex2f(-d0 * d0);
        s1 += ex2f(-d1 * d1);
        s2 += ex2f(-d2 * d2);
        s3 += ex2f(-d3 * d3);
    }

    if (j < n) g_part[blockIdx.y * NMAX + j] = (s0 + s1) + (s2 + s3);
}

// ---------------------------------------------------------------------------
// Kernel 2: mixture_pdf, assemble data_pdf, squared-error block reduction.
// ---------------------------------------------------------------------------
__global__ void k_final(const float* __restrict__ x,
                        const float* __restrict__ means,
                        float* __restrict__ out,
                        int n, int K, float invC) {
    __shared__ float cA[KMAX], cB[KMAX], mu[KMAX];
    __shared__ float red[BLK];
    int t = threadIdx.x;
    if (t < K) {
        cA[t] = g_coefA[t];
        cB[t] = g_coefB[t];
        mu[t] = means[t];
    }
    __syncthreads();

    int j = blockIdx.x * BLK + t;
    float val = 0.0f;
    if (j < n) {
        float xj = x[j];
        float mix = 0.0f;
#pragma unroll 8
        for (int k = 0; k < KMAX; k++) {
            if (k < K) {
                float d = xj - mu[k];
                mix += cA[k] * __expf(cB[k] * d * d);
            }
        }
        float data = 0.0f;
#pragma unroll
        for (int c = 0; c < ICHUNKS; c++) data += g_part[c * NMAX + j];
        data *= invC;
        float e = mix - data;
        val = e * e;
    }

    red[t] = val;
    __syncthreads();
#pragma unroll
    for (int o = BLK / 2; o > 0; o >>= 1) {
        if (t < o) red[t] += red[t + o];
        __syncthreads();
    }
    if (t == 0) atomicAdd(out, red[0]);
}

// ---------------------------------------------------------------------------
extern "C" void kernel_launch(void* const* d_in, const int* in_sizes, int n_in,
                              void* d_out, int out_size) {
    const float* x     = (const float*)d_in[0];
    const float* wl    = (const float*)d_in[1];
    const float* means = (const float*)d_in[2];
    const float* lv    = (const float*)d_in[3];
    float* out = (float*)d_out;

    int n = in_sizes[0];   // 8192
    int K = in_sizes[1];   // 64

    // bandwidth = 0.5 * 128 / n  (= 2^-7 for n = 8192)
    double bw   = 64.0 / (double)n;
    double bw2  = bw * bw;
    double Ckde = -0.5 / bw2;                                  // -8192 for n=8192
    double LOG2E = 1.4426950408889634;
    float  scaleS = (float)sqrt(-Ckde * LOG2E);                // exp2-domain prescale
    float  invC   = (float)(1.0 / (sqrt(2.0 * M_PI * bw2) * (double)n));

    k_prep<<<1, KMAX>>>(wl, lv, out, K);

    dim3 g((n + BLK - 1) / BLK, ICHUNKS);
    k_kde<<<g, BLK>>>(x, n, scaleS);

    k_final<<<(n + BLK - 1) / BLK, BLK>>>(x, means, out, n, K, invC);
}